// round 2
// baseline (speedup 1.0000x reference)
#include <cuda_runtime.h>
#include <math.h>
#include <float.h>

// Problem shape (fixed by the reference)
constexpr int B_ = 2;
constexpr int C_ = 16;
constexpr int D_ = 80;
constexpr int H_ = 96;
constexpr int W_ = 96;
constexpr int DHW = D_ * H_ * W_;          // 737280
constexpr int SP  = B_ * DHW;              // 1474560  (spatial sites)
constexpr size_t TEN = (size_t)B_ * C_ * DHW; // 23592960 (elements per tensor)

// Scratch: pooled fields  [pmax_fix, pavg_fix, pmax_move, pavg_move]
__device__ float g_pool[4 * SP];

// ---------------------------------------------------------------------------
// Kernel 1: channel max/avg pooling for both tensors
// ---------------------------------------------------------------------------
__global__ __launch_bounds__(256)
void pool_kernel(const float* __restrict__ fix, const float* __restrict__ mov) {
    int gid = blockIdx.x * blockDim.x + threadIdx.x;
    if (gid >= SP) return;
    int b = gid / DHW;
    int s = gid - b * DHW;
    const float* pf = fix + (size_t)b * C_ * DHW + s;
    const float* pm = mov + (size_t)b * C_ * DHW + s;

    float mxf = -FLT_MAX, smf = 0.f, mxm = -FLT_MAX, smm = 0.f;
#pragma unroll
    for (int c = 0; c < C_; c++) {
        float v = pf[c * DHW];
        mxf = fmaxf(mxf, v);
        smf += v;
        float u = pm[c * DHW];
        mxm = fmaxf(mxm, u);
        smm += u;
    }
    g_pool[0 * SP + gid] = mxf;
    g_pool[1 * SP + gid] = smf * (1.f / 16.f);
    g_pool[2 * SP + gid] = mxm;
    g_pool[3 * SP + gid] = smm * (1.f / 16.f);
}

// ---------------------------------------------------------------------------
// Kernel 2: 7x7x7 conv (2ch) + sigmoid + cross-gated residual, fused
// Tile: 32(W) x 8(H) x 4(D) outputs, 256 threads, 4 outputs/thread along W
// ---------------------------------------------------------------------------
constexpr int TW = 32, TH = 8, TD = 4;
constexpr int HX = TW + 6;   // 38 valid halo width
constexpr int HXS = 40;      // padded stride (float4 alignment)
constexpr int HY = TH + 6;   // 14
constexpr int HZ = TD + 6;   // 10

__global__ __launch_bounds__(256)
void conv_apply_kernel(const float* __restrict__ fix, const float* __restrict__ mov,
                       const float* __restrict__ w_f2m, const float* __restrict__ w_m2f,
                       float* __restrict__ out) {
    __shared__ float s_ch[2][HZ * HY * HXS];  // 2 x 5600 floats = 44.8 KB
    __shared__ float s_w[686];                //  2.7 KB

    const int tx = threadIdx.x;  // 0..7  (W groups of 4)
    const int ty = threadIdx.y;  // 0..7  (H)
    const int tz = threadIdx.z;  // 0..3  (D)
    const int tid = tx + ty * 8 + tz * 64;

    const int x0 = blockIdx.x * TW;
    const int y0 = blockIdx.y * TH;
    const int bz = blockIdx.z;
    const int b  = bz / (D_ / TD);
    const int z0 = (bz - b * (D_ / TD)) * TD;

    float acc[2][4];
#pragma unroll
    for (int g = 0; g < 2; g++)
#pragma unroll
        for (int r = 0; r < 4; r++) acc[g][r] = 0.f;

    const float* wsrc[2] = {w_f2m, w_m2f};

#pragma unroll
    for (int g = 0; g < 2; g++) {
        // ---- load halo (both conv channels: max, avg) for this gate ----
        const float* pmax = g_pool + (size_t)(2 * g + 0) * SP + (size_t)b * DHW;
        const float* pavg = g_pool + (size_t)(2 * g + 1) * SP + (size_t)b * DHW;
        for (int i = tid; i < HZ * HY * HX; i += 256) {
            int dz  = i / (HY * HX);
            int rem = i - dz * (HY * HX);
            int dy  = rem / HX;
            int dx  = rem - dy * HX;
            int gz = z0 + dz - 3, gy = y0 + dy - 3, gx = x0 + dx - 3;
            float vmax = 0.f, vavg = 0.f;
            if (gz >= 0 && gz < D_ && gy >= 0 && gy < H_ && gx >= 0 && gx < W_) {
                int off = (gz * H_ + gy) * W_ + gx;
                vmax = pmax[off];
                vavg = pavg[off];
            }
            int so = (dz * HY + dy) * HXS + dx;
            s_ch[0][so] = vmax;
            s_ch[1][so] = vavg;
        }
        for (int i = tid; i < 686; i += 256) s_w[i] = wsrc[g][i];
        __syncthreads();

        // ---- conv: each thread does 4 W-adjacent outputs ----
#pragma unroll 1
        for (int c = 0; c < 2; c++) {
#pragma unroll 1
            for (int kz = 0; kz < 7; kz++) {
                const float* slab = &s_ch[c][(tz + kz) * HY * HXS];
                const float* wpl  = &s_w[c * 343 + kz * 49];
#pragma unroll
                for (int ky = 0; ky < 7; ky++) {
                    const float* row = &slab[(ty + ky) * HXS + tx * 4];
                    float4 v0 = *reinterpret_cast<const float4*>(row);
                    float4 v1 = *reinterpret_cast<const float4*>(row + 4);
                    float2 v2 = *reinterpret_cast<const float2*>(row + 8);
                    float rv[10] = {v0.x, v0.y, v0.z, v0.w,
                                    v1.x, v1.y, v1.z, v1.w,
                                    v2.x, v2.y};
                    const float* wr = &wpl[ky * 7];
#pragma unroll
                    for (int kx = 0; kx < 7; kx++) {
                        float wv = wr[kx];
#pragma unroll
                        for (int r = 0; r < 4; r++)
                            acc[g][r] = fmaf(rv[kx + r], wv, acc[g][r]);
                    }
                }
            }
        }
        __syncthreads();  // protect smem before next gate overwrites
    }

    // ---- sigmoid gates ----
    float saf[4], sam[4];
#pragma unroll
    for (int r = 0; r < 4; r++) {
        saf[r] = 1.f / (1.f + expf(-acc[0][r]));
        sam[r] = 1.f / (1.f + expf(-acc[1][r]));
    }

    // ---- apply: fix_out = mov*sa_fix + fix ; move_out = fix*sa_move + mov ----
    const int z = z0 + tz, y = y0 + ty, x = x0 + tx * 4;
    const size_t sbase = (size_t)b * C_ * DHW + (size_t)(z * H_ + y) * W_ + x;
    float* out_f = out;
    float* out_m = out + TEN;

#pragma unroll 1
    for (int c = 0; c < C_; c++) {
        size_t o = sbase + (size_t)c * DHW;
        float4 f = *reinterpret_cast<const float4*>(fix + o);
        float4 m = *reinterpret_cast<const float4*>(mov + o);
        float4 of, om;
        of.x = fmaf(m.x, saf[0], f.x);  om.x = fmaf(f.x, sam[0], m.x);
        of.y = fmaf(m.y, saf[1], f.y);  om.y = fmaf(f.y, sam[1], m.y);
        of.z = fmaf(m.z, saf[2], f.z);  om.z = fmaf(f.z, sam[2], m.z);
        of.w = fmaf(m.w, saf[3], f.w);  om.w = fmaf(f.w, sam[3], m.w);
        *reinterpret_cast<float4*>(out_f + o) = of;
        *reinterpret_cast<float4*>(out_m + o) = om;
    }
}

// ---------------------------------------------------------------------------
extern "C" void kernel_launch(void* const* d_in, const int* in_sizes, int n_in,
                              void* d_out, int out_size) {
    const float* fix   = (const float*)d_in[0];
    const float* mov   = (const float*)d_in[1];
    const float* w_f2m = (const float*)d_in[2];
    const float* w_m2f = (const float*)d_in[3];
    float* out = (float*)d_out;

    // Pass 1: pooling
    {
        int threads = 256;
        int blocks = (SP + threads - 1) / threads;
        pool_kernel<<<blocks, threads>>>(fix, mov);
    }
    // Pass 2: conv + sigmoid + gated residual
    {
        dim3 block(8, 8, 4);
        dim3 grid(W_ / TW, H_ / TH, B_ * (D_ / TD));  // 3 x 12 x 40
        conv_apply_kernel<<<grid, block>>>(fix, mov, w_f2m, w_m2f, out);
    }
}